// round 6
// baseline (speedup 1.0000x reference)
#include <cuda_runtime.h>
#include <cstddef>

#define DEVFN __device__ __forceinline__

namespace {
constexpr int Bsz  = 4096;
constexpr int Tlen = 512;
constexpr int IND  = 64;

// S row layout: x[0,64) h1[64,154) h2[154,220) h3[220,268) h4[268,292)
constexpr int WT_TOTAL = 125424;
constexpr int B_TOTAL  = 912;

constexpr int SROWS = 292;
constexpr int CROWS = 228;
constexpr int SDIM  = 34;   // padded row stride (floats); even -> 8B-aligned float2
constexpr int MTILE = 32;
constexpr int NTHREADS = 512;
constexpr int NBLOCKS  = Bsz / MTILE;           // 128
constexpr int SMEM_BYTES = (SROWS + CROWS) * SDIM * 4;  // 70720
constexpr int H4OFF = 268;  // h4 row offset in S
}

// Transposed combined weights [K][4H] per layer + fused bias (bih+bhh)
__device__ float g_WT[WT_TOTAL];
__device__ float g_Bias[B_TOTAL];

// ---------------------------------------------------------------------------
// Prep kernel: transpose weights into [k][n] layout, fuse biases.
// All layer tables are FUNCTION-LOCAL (runtime-indexable in device code).
// ---------------------------------------------------------------------------
__global__ void prep_kernel(
    const float* __restrict__ Wih1, const float* __restrict__ Whh1,
    const float* __restrict__ bih1, const float* __restrict__ bhh1,
    const float* __restrict__ Wih2, const float* __restrict__ Whh2,
    const float* __restrict__ bih2, const float* __restrict__ bhh2,
    const float* __restrict__ Wih3, const float* __restrict__ Whh3,
    const float* __restrict__ bih3, const float* __restrict__ bhh3,
    const float* __restrict__ Wih4, const float* __restrict__ Whh4,
    const float* __restrict__ bih4, const float* __restrict__ bhh4)
{
    const float* Wih[4] = {Wih1, Wih2, Wih3, Wih4};
    const float* Whh[4] = {Whh1, Whh2, Whh3, Whh4};
    const float* bih[4] = {bih1, bih2, bih3, bih4};
    const float* bhh[4] = {bhh1, bhh2, bhh3, bhh4};

    const int lH[4]    = {90, 66, 48, 24};
    const int lDIN[4]  = {64, 90, 66, 48};
    const int lWOFF[4] = {0, 55440, 96624, 118512};
    const int lBOFF[4] = {0, 360, 624, 816};

    int idx = blockIdx.x * blockDim.x + threadIdx.x;
    if (idx < WT_TOTAL) {
        int l = (idx < lWOFF[1]) ? 0 : (idx < lWOFF[2]) ? 1 : (idx < lWOFF[3]) ? 2 : 3;
        int r = idx - lWOFF[l];
        int N = 4 * lH[l];
        int k = r / N;
        int n = r % N;
        float v;
        if (k < lDIN[l]) v = Wih[l][n * lDIN[l] + k];
        else             v = Whh[l][n * lH[l] + (k - lDIN[l])];
        g_WT[idx] = v;
    } else if (idx < WT_TOTAL + B_TOTAL) {
        int bi = idx - WT_TOTAL;
        int l = (bi < lBOFF[1]) ? 0 : (bi < lBOFF[2]) ? 1 : (bi < lBOFF[3]) ? 2 : 3;
        int n = bi - lBOFF[l];
        g_Bias[bi] = bih[l][n] + bhh[l][n];
    }
}

// ---------------------------------------------------------------------------
// f32x2 helpers (packed fp32 FMA -> 2x FFMA issue rate on sm_100a)
// ---------------------------------------------------------------------------
DEVFN unsigned long long pk2(float lo, float hi) {
    unsigned long long u;
    asm("mov.b64 %0, {%1, %2};" : "=l"(u) : "f"(lo), "f"(hi));
    return u;
}
DEVFN float2 un2(unsigned long long u) {
    float2 v;
    asm("mov.b64 {%0, %1}, %2;" : "=f"(v.x), "=f"(v.y) : "l"(u));
    return v;
}
DEVFN void fma2(unsigned long long& d, unsigned long long a, unsigned long long b) {
    asm("fma.rn.f32x2 %0, %1, %2, %0;" : "+l"(d) : "l"(a), "l"(b));
}
DEVFN float sigf(float x)     { return __fdividef(1.0f, 1.0f + __expf(-x)); }
DEVFN float tanhfast(float x) { return __fdividef(2.0f, 1.0f + __expf(-2.0f * x)) - 1.0f; }

// ---------------------------------------------------------------------------
// One LSTM layer step: GEMM (gates) + cell update, in-place in smem.
// Thread (w, jo, moct): unit j = 8*w + jo, batch rows m = moct*8 .. moct*8+7.
// ALL layer constants are non-type template parameters — no constexpr-array
// references anywhere in device code.
//   HH: hidden size, KK: DIN+HH, SO: GEMM input row window start in S,
//   HO: h row offset in S, CO: c row offset in C,
//   WO: weight offset in g_WT, BO: bias offset in g_Bias.
// ---------------------------------------------------------------------------
template <int HH, int KK, int SO, int HO, int CO, int WO, int BO>
DEVFN void layer_step(float* __restrict__ S, float* __restrict__ C,
                      int w, int jo, int moct)
{
    constexpr int NN  = 4 * HH;
    constexpr int SDH = SDIM / 2;   // 17 (ull units per row)

    const int j = 8 * w + jo;
    const bool on = (j < HH);

    unsigned long long acc[4][4];   // [gate i,f,g,o][m-pair]

    if (on) {
#pragma unroll
        for (int g = 0; g < 4; ++g) {
            float bv = g_Bias[BO + g * HH + j];
            unsigned long long bb = pk2(bv, bv);
#pragma unroll
            for (int p = 0; p < 4; ++p) acc[g][p] = bb;
        }
        const float* __restrict__ pw = g_WT + WO + j;
        const unsigned long long* __restrict__ pa =
            reinterpret_cast<const unsigned long long*>(S) + SO * SDH + moct * 4;

#pragma unroll 4
        for (int k = 0; k < KK; ++k) {
            const float* wk = pw + k * NN;
            float w0 = __ldg(wk);
            float w1 = __ldg(wk + HH);
            float w2 = __ldg(wk + 2 * HH);
            float w3 = __ldg(wk + 3 * HH);
            const unsigned long long* ak = pa + k * SDH;
            unsigned long long a0 = ak[0], a1 = ak[1], a2 = ak[2], a3 = ak[3];
            unsigned long long p0 = pk2(w0, w0);
            unsigned long long p1 = pk2(w1, w1);
            unsigned long long p2 = pk2(w2, w2);
            unsigned long long p3 = pk2(w3, w3);
            fma2(acc[0][0], a0, p0); fma2(acc[0][1], a1, p0);
            fma2(acc[0][2], a2, p0); fma2(acc[0][3], a3, p0);
            fma2(acc[1][0], a0, p1); fma2(acc[1][1], a1, p1);
            fma2(acc[1][2], a2, p1); fma2(acc[1][3], a3, p1);
            fma2(acc[2][0], a0, p2); fma2(acc[2][1], a1, p2);
            fma2(acc[2][2], a2, p2); fma2(acc[2][3], a3, p2);
            fma2(acc[3][0], a0, p3); fma2(acc[3][1], a1, p3);
            fma2(acc[3][2], a2, p3); fma2(acc[3][3], a3, p3);
        }
    }
    __syncthreads();   // all GEMM reads of S (incl. old h of this layer) done

    if (on) {
#pragma unroll
        for (int p = 0; p < 4; ++p) {
            float2 iv = un2(acc[0][p]);
            float2 fv = un2(acc[1][p]);
            float2 gv = un2(acc[2][p]);
            float2 ov = un2(acc[3][p]);
            float* cp = C + (CO + j) * SDIM + moct * 8 + 2 * p;
            float2 cv = *reinterpret_cast<const float2*>(cp);
            float c0 = sigf(fv.x) * cv.x + sigf(iv.x) * tanhfast(gv.x);
            float c1 = sigf(fv.y) * cv.y + sigf(iv.y) * tanhfast(gv.y);
            float h0 = sigf(ov.x) * tanhfast(c0);
            float h1 = sigf(ov.y) * tanhfast(c1);
            *reinterpret_cast<float2*>(cp) = make_float2(c0, c1);
            *reinterpret_cast<float2*>(S + (HO + j) * SDIM + moct * 8 + 2 * p) =
                make_float2(h0, h1);
        }
    }
    __syncthreads();   // new h visible before next layer reads
}

// ---------------------------------------------------------------------------
// Persistent main kernel: one CTA = 32 batch rows, full T loop.
// ---------------------------------------------------------------------------
__global__ void __launch_bounds__(NTHREADS, 1)
lstm_main(const float* __restrict__ x,
          const float* __restrict__ fcw,
          const float* __restrict__ fcb,
          float* __restrict__ out)
{
    extern __shared__ float sm[];
    float* S = sm;                        // SROWS x SDIM
    float* C = sm + SROWS * SDIM;         // CROWS x SDIM

    const int tid  = threadIdx.x;
    const int w    = tid >> 5;
    const int lane = tid & 31;
    const int moct = lane >> 3;
    const int jo   = lane & 7;
    const int b0   = blockIdx.x * MTILE;

    for (int i = tid; i < (SROWS + CROWS) * SDIM; i += NTHREADS) sm[i] = 0.0f;
    __syncthreads();

    // warp w loads x[:, t, 4w .. 4w+3], lane = batch row m
    const float* xrow = x + (size_t)(b0 + lane) * Tlen * IND + 4 * w;

    for (int t = 0; t < Tlen; ++t) {
        float4 xv = *reinterpret_cast<const float4*>(xrow + (size_t)t * IND);
        S[(4 * w + 0) * SDIM + lane] = xv.x;
        S[(4 * w + 1) * SDIM + lane] = xv.y;
        S[(4 * w + 2) * SDIM + lane] = xv.z;
        S[(4 * w + 3) * SDIM + lane] = xv.w;
        __syncthreads();

        //            HH  KK   SO   HO   CO   WO      BO
        layer_step<90, 154,   0,  64,   0,      0,   0>(S, C, w, jo, moct);
        layer_step<66, 156,  64, 154,  90,  55440, 360>(S, C, w, jo, moct);
        layer_step<48, 114, 154, 220, 156,  96624, 624>(S, C, w, jo, moct);
        layer_step<24,  72, 220, 268, 204, 118512, 816>(S, C, w, jo, moct);
    }

    // final FC: out[b] = h4[b,:] . fcw + fcb
    if (tid < 32) {
        float acc = fcb[0];
#pragma unroll
        for (int jj = 0; jj < 24; ++jj)
            acc += S[(H4OFF + jj) * SDIM + tid] * fcw[jj];
        out[b0 + tid] = acc;
    }
}

// ---------------------------------------------------------------------------
extern "C" void kernel_launch(void* const* d_in, const int* in_sizes, int n_in,
                              void* d_out, int out_size)
{
    (void)in_sizes; (void)n_in; (void)out_size;
    const float* x    = (const float*)d_in[0];
    const float* Wih1 = (const float*)d_in[1];
    const float* Whh1 = (const float*)d_in[2];
    const float* bih1 = (const float*)d_in[3];
    const float* bhh1 = (const float*)d_in[4];
    const float* Wih2 = (const float*)d_in[5];
    const float* Whh2 = (const float*)d_in[6];
    const float* bih2 = (const float*)d_in[7];
    const float* bhh2 = (const float*)d_in[8];
    const float* Wih3 = (const float*)d_in[9];
    const float* Whh3 = (const float*)d_in[10];
    const float* bih3 = (const float*)d_in[11];
    const float* bhh3 = (const float*)d_in[12];
    const float* Wih4 = (const float*)d_in[13];
    const float* Whh4 = (const float*)d_in[14];
    const float* bih4 = (const float*)d_in[15];
    const float* bhh4 = (const float*)d_in[16];
    const float* fcw  = (const float*)d_in[17];
    const float* fcb  = (const float*)d_in[18];

    static bool attr_done = false;
    if (!attr_done) {
        cudaFuncSetAttribute(lstm_main,
                             cudaFuncAttributeMaxDynamicSharedMemorySize,
                             SMEM_BYTES);
        attr_done = true;
    }

    const int prep_total = WT_TOTAL + B_TOTAL;
    prep_kernel<<<(prep_total + 255) / 256, 256>>>(
        Wih1, Whh1, bih1, bhh1, Wih2, Whh2, bih2, bhh2,
        Wih3, Whh3, bih3, bhh3, Wih4, Whh4, bih4, bhh4);

    lstm_main<<<NBLOCKS, NTHREADS, SMEM_BYTES>>>(x, fcw, fcb, (float*)d_out);
}

// round 7
// speedup vs baseline: 1.0689x; 1.0689x over previous
#include <cuda_runtime.h>
#include <cstddef>

#define DEVFN __device__ __forceinline__

namespace {
constexpr int Bsz  = 4096;
constexpr int Tlen = 512;
constexpr int IND  = 64;

constexpr int WT_TOTAL = 125424;
constexpr int B_TOTAL  = 912;

// S row layout: x[0,64) h1[64,154) h2[154,220) h3[220,268) h4[268,292)
constexpr int SROWS = 292;
constexpr int CROWS = 228;
constexpr int SDIM  = 36;    // 144B row stride -> 16B-aligned float4/ulonglong2
constexpr int MTILE = 32;
constexpr int NTHREADS = 512;
constexpr int NBLOCKS  = Bsz / MTILE;          // 128

// smem layout (float offsets)
constexpr int C_OFF   = SROWS * SDIM;          // 10512
constexpr int WL2_OFF = C_OFF + CROWS * SDIM;  // 18720  (layer-2 weights: 114*48*4)
constexpr int WL3_OFF = WL2_OFF + 21888;       // 40608  (layer-3 weights: 72*24*4)
constexpr int SMEM_FLOATS = WL3_OFF + 6912;    // 47520
constexpr int SMEM_BYTES  = SMEM_FLOATS * 4;   // 190080 (< 227KB)

constexpr int H4OFF = 268;
}

// Weights, gate-interleaved: g_WT[WO + (k*HH + j)*4 + g], g in {i,f,g,o}.
__device__ __align__(16) float g_WT[WT_TOTAL];
__device__ float g_Bias[B_TOTAL];   // [layer][gate][unit], gate-major per layer

// ---------------------------------------------------------------------------
// Prep kernel: transpose to gate-interleaved [k][j][4] layout, fuse biases.
// ---------------------------------------------------------------------------
__global__ void prep_kernel(
    const float* __restrict__ Wih1, const float* __restrict__ Whh1,
    const float* __restrict__ bih1, const float* __restrict__ bhh1,
    const float* __restrict__ Wih2, const float* __restrict__ Whh2,
    const float* __restrict__ bih2, const float* __restrict__ bhh2,
    const float* __restrict__ Wih3, const float* __restrict__ Whh3,
    const float* __restrict__ bih3, const float* __restrict__ bhh3,
    const float* __restrict__ Wih4, const float* __restrict__ Whh4,
    const float* __restrict__ bih4, const float* __restrict__ bhh4)
{
    const float* Wih[4] = {Wih1, Wih2, Wih3, Wih4};
    const float* Whh[4] = {Whh1, Whh2, Whh3, Whh4};
    const float* bih[4] = {bih1, bih2, bih3, bih4};
    const float* bhh[4] = {bhh1, bhh2, bhh3, bhh4};

    const int lH[4]    = {90, 66, 48, 24};
    const int lDIN[4]  = {64, 90, 66, 48};
    const int lWOFF[4] = {0, 55440, 96624, 118512};
    const int lBOFF[4] = {0, 360, 624, 816};

    int idx = blockIdx.x * blockDim.x + threadIdx.x;
    if (idx < WT_TOTAL) {
        int l = (idx < lWOFF[1]) ? 0 : (idx < lWOFF[2]) ? 1 : (idx < lWOFF[3]) ? 2 : 3;
        int r  = idx - lWOFF[l];
        int f4 = r >> 2;
        int g  = r & 3;
        int k  = f4 / lH[l];
        int j  = f4 % lH[l];
        int n  = g * lH[l] + j;          // row in the original [4H, DIN/H] matrices
        float v;
        if (k < lDIN[l]) v = Wih[l][n * lDIN[l] + k];
        else             v = Whh[l][n * lH[l] + (k - lDIN[l])];
        g_WT[idx] = v;
    } else if (idx < WT_TOTAL + B_TOTAL) {
        int bi = idx - WT_TOTAL;
        int l = (bi < lBOFF[1]) ? 0 : (bi < lBOFF[2]) ? 1 : (bi < lBOFF[3]) ? 2 : 3;
        int n = bi - lBOFF[l];
        g_Bias[bi] = bih[l][n] + bhh[l][n];
    }
}

// ---------------------------------------------------------------------------
// f32x2 helpers
// ---------------------------------------------------------------------------
DEVFN unsigned long long pk2(float lo, float hi) {
    unsigned long long u;
    asm("mov.b64 %0, {%1, %2};" : "=l"(u) : "f"(lo), "f"(hi));
    return u;
}
DEVFN float2 un2(unsigned long long u) {
    float2 v;
    asm("mov.b64 {%0, %1}, %2;" : "=f"(v.x), "=f"(v.y) : "l"(u));
    return v;
}
DEVFN void fma2(unsigned long long& d, unsigned long long a, unsigned long long b) {
    asm("fma.rn.f32x2 %0, %1, %2, %0;" : "+l"(d) : "l"(a), "l"(b));
}
DEVFN float sigf(float x)     { return __fdividef(1.0f, 1.0f + __expf(-x)); }
DEVFN float tanhfast(float x) { return __fdividef(2.0f, 1.0f + __expf(-2.0f * x)) - 1.0f; }

// ---------------------------------------------------------------------------
// One LSTM layer step. GL selects global (__ldg) vs shared weight loads.
// wj: weight base pre-offset by j, in float4 units; element k at wj[k*HH].
// ---------------------------------------------------------------------------
template <int HH, int KK, int SO, int HO, int CO, int BO, bool GL>
DEVFN void layer_step(float* __restrict__ S, float* __restrict__ C,
                      const float4* __restrict__ wj,
                      int j, bool on, int moct)
{
    unsigned long long acc[4][4];   // [gate i,f,g,o][batch pair]

    if (on) {
#pragma unroll
        for (int g = 0; g < 4; ++g) {
            float bv = g_Bias[BO + g * HH + j];
            unsigned long long bb = pk2(bv, bv);
#pragma unroll
            for (int p = 0; p < 4; ++p) acc[g][p] = bb;
        }
        const ulonglong2* __restrict__ pa =
            reinterpret_cast<const ulonglong2*>(S) + SO * (SDIM / 4) + moct * 2;

#pragma unroll 4
        for (int k = 0; k < KK; ++k) {
            float4 wv = GL ? __ldg(wj + k * HH) : wj[k * HH];
            ulonglong2 u0 = pa[k * (SDIM / 4)];
            ulonglong2 u1 = pa[k * (SDIM / 4) + 1];
            unsigned long long p0 = pk2(wv.x, wv.x);
            unsigned long long p1 = pk2(wv.y, wv.y);
            unsigned long long p2 = pk2(wv.z, wv.z);
            unsigned long long p3 = pk2(wv.w, wv.w);
            fma2(acc[0][0], u0.x, p0); fma2(acc[0][1], u0.y, p0);
            fma2(acc[0][2], u1.x, p0); fma2(acc[0][3], u1.y, p0);
            fma2(acc[1][0], u0.x, p1); fma2(acc[1][1], u0.y, p1);
            fma2(acc[1][2], u1.x, p1); fma2(acc[1][3], u1.y, p1);
            fma2(acc[2][0], u0.x, p2); fma2(acc[2][1], u0.y, p2);
            fma2(acc[2][2], u1.x, p2); fma2(acc[2][3], u1.y, p2);
            fma2(acc[3][0], u0.x, p3); fma2(acc[3][1], u0.y, p3);
            fma2(acc[3][2], u1.x, p3); fma2(acc[3][3], u1.y, p3);
        }
    }
    __syncthreads();   // all reads of S (incl. this layer's old h) complete

    if (on) {
        float* cp = C + (CO + j) * SDIM + moct * 8;
        float cold[8], cn[8], hn[8];
        *reinterpret_cast<float4*>(cold)     = *reinterpret_cast<const float4*>(cp);
        *reinterpret_cast<float4*>(cold + 4) = *reinterpret_cast<const float4*>(cp + 4);
#pragma unroll
        for (int p = 0; p < 4; ++p) {
            float2 iv = un2(acc[0][p]);
            float2 fv = un2(acc[1][p]);
            float2 gv = un2(acc[2][p]);
            float2 ov = un2(acc[3][p]);
            float c0 = sigf(fv.x) * cold[2 * p]     + sigf(iv.x) * tanhfast(gv.x);
            float c1 = sigf(fv.y) * cold[2 * p + 1] + sigf(iv.y) * tanhfast(gv.y);
            cn[2 * p]     = c0;
            cn[2 * p + 1] = c1;
            hn[2 * p]     = sigf(ov.x) * tanhfast(c0);
            hn[2 * p + 1] = sigf(ov.y) * tanhfast(c1);
        }
        *reinterpret_cast<float4*>(cp)     = *reinterpret_cast<const float4*>(cn);
        *reinterpret_cast<float4*>(cp + 4) = *reinterpret_cast<const float4*>(cn + 4);
        float* hp = S + (HO + j) * SDIM + moct * 8;
        *reinterpret_cast<float4*>(hp)     = *reinterpret_cast<const float4*>(hn);
        *reinterpret_cast<float4*>(hp + 4) = *reinterpret_cast<const float4*>(hn + 4);
    }
    __syncthreads();   // new h visible to the next layer
}

// ---------------------------------------------------------------------------
// Persistent main kernel: one CTA = 32 batch rows, full T loop.
// ---------------------------------------------------------------------------
__global__ void __launch_bounds__(NTHREADS, 1)
lstm_main(const float* __restrict__ x,
          const float* __restrict__ fcw,
          const float* __restrict__ fcb,
          float* __restrict__ out)
{
    extern __shared__ float sm[];
    float* S = sm;                 // SROWS x SDIM
    float* C = sm + C_OFF;         // CROWS x SDIM

    const int tid  = threadIdx.x;
    const int w    = tid >> 5;
    const int lane = tid & 31;
    const int moct = lane >> 3;
    const int jo   = lane & 7;
    const int j    = 8 * w + jo;
    const int b0   = blockIdx.x * MTILE;

    // stage layer-2/3 weights into smem (linear float4 copy; layout identical)
    {
        const float4* gw4 = reinterpret_cast<const float4*>(g_WT);
        float4* w2 = reinterpret_cast<float4*>(sm + WL2_OFF);
        float4* w3 = reinterpret_cast<float4*>(sm + WL3_OFF);
        for (int i = tid; i < 5472; i += NTHREADS) w2[i] = gw4[24156 + i]; // 96624/4
        for (int i = tid; i < 1728; i += NTHREADS) w3[i] = gw4[29628 + i]; // 118512/4
    }
    // zero states
    for (int i = tid; i < WL2_OFF; i += NTHREADS) sm[i] = 0.0f;
    __syncthreads();

    const float4* gw = reinterpret_cast<const float4*>(g_WT);
    const float4* wj0 = gw + j;                                        // L0 (global)
    const float4* wj1 = gw + 13860 + j;                                // L1 (global)
    const float4* wj2 = reinterpret_cast<const float4*>(sm + WL2_OFF) + j;  // L2 (smem)
    const float4* wj3 = reinterpret_cast<const float4*>(sm + WL3_OFF) + j;  // L3 (smem)
    const bool on0 = (j < 90), on1 = (j < 66), on2 = (j < 48), on3 = (j < 24);

    // warp w loads x[:, t, 4w .. 4w+3], lane = batch row m
    const float* xrow = x + (size_t)(b0 + lane) * Tlen * IND + 4 * w;

    for (int t = 0; t < Tlen; ++t) {
        float4 xv = *reinterpret_cast<const float4*>(xrow + (size_t)t * IND);
        S[(4 * w + 0) * SDIM + lane] = xv.x;
        S[(4 * w + 1) * SDIM + lane] = xv.y;
        S[(4 * w + 2) * SDIM + lane] = xv.z;
        S[(4 * w + 3) * SDIM + lane] = xv.w;
        __syncthreads();

        //         HH  KK   SO   HO   CO   BO    GL
        layer_step<90, 154,   0,  64,   0,   0, true >(S, C, wj0, j, on0, moct);
        layer_step<66, 156,  64, 154,  90, 360, true >(S, C, wj1, j, on1, moct);
        layer_step<48, 114, 154, 220, 156, 624, false>(S, C, wj2, j, on2, moct);
        layer_step<24,  72, 220, 268, 204, 816, false>(S, C, wj3, j, on3, moct);
    }

    // final FC: out[b] = h4[b,:] . fcw + fcb
    if (tid < 32) {
        float acc = fcb[0];
#pragma unroll
        for (int jj = 0; jj < 24; ++jj)
            acc += S[(H4OFF + jj) * SDIM + tid] * fcw[jj];
        out[b0 + tid] = acc;
    }
}

// ---------------------------------------------------------------------------
extern "C" void kernel_launch(void* const* d_in, const int* in_sizes, int n_in,
                              void* d_out, int out_size)
{
    (void)in_sizes; (void)n_in; (void)out_size;
    const float* x    = (const float*)d_in[0];
    const float* Wih1 = (const float*)d_in[1];
    const float* Whh1 = (const float*)d_in[2];
    const float* bih1 = (const float*)d_in[3];
    const float* bhh1 = (const float*)d_in[4];
    const float* Wih2 = (const float*)d_in[5];
    const float* Whh2 = (const float*)d_in[6];
    const float* bih2 = (const float*)d_in[7];
    const float* bhh2 = (const float*)d_in[8];
    const float* Wih3 = (const float*)d_in[9];
    const float* Whh3 = (const float*)d_in[10];
    const float* bih3 = (const float*)d_in[11];
    const float* bhh3 = (const float*)d_in[12];
    const float* Wih4 = (const float*)d_in[13];
    const float* Whh4 = (const float*)d_in[14];
    const float* bih4 = (const float*)d_in[15];
    const float* bhh4 = (const float*)d_in[16];
    const float* fcw  = (const float*)d_in[17];
    const float* fcb  = (const float*)d_in[18];

    static bool attr_done = false;
    if (!attr_done) {
        cudaFuncSetAttribute(lstm_main,
                             cudaFuncAttributeMaxDynamicSharedMemorySize,
                             SMEM_BYTES);
        attr_done = true;
    }

    const int prep_total = WT_TOTAL + B_TOTAL;
    prep_kernel<<<(prep_total + 255) / 256, 256>>>(
        Wih1, Whh1, bih1, bhh1, Wih2, Whh2, bih2, bhh2,
        Wih3, Whh3, bih3, bhh3, Wih4, Whh4, bih4, bhh4);

    lstm_main<<<NBLOCKS, NTHREADS, SMEM_BYTES>>>(x, fcw, fcb, (float*)d_out);
}

// round 10
// speedup vs baseline: 2.0624x; 1.9294x over previous
#include <cuda_runtime.h>
#include <cstddef>

#define DEVFN __device__ __forceinline__

namespace {
constexpr int Bsz  = 4096;
constexpr int Tlen = 512;
constexpr int IND  = 64;

constexpr int WT_TOTAL = 125424;
constexpr int B_TOTAL  = 912;

// state row layout (per parity): x[0,64) h1[64,154) h2[154,220) h3[220,268) h4[268,292)
constexpr int SROWS = 292;
constexpr int SDIM  = 36;                      // 144B rows, 16B aligned
constexpr int PSTRIDE = SROWS * SDIM;          // 10512 floats per parity
constexpr int MTILE = 32;
constexpr int NTHREADS = 512;
constexpr int NBLOCKS  = Bsz / MTILE;          // 128
constexpr int NSTAGES  = Tlen + 3;             // 515

// smem layout (float offsets): parity0 | parity1 | WL2 | WL3
constexpr int WL2_OFF = 2 * PSTRIDE;           // 21024
constexpr int WL3_OFF = WL2_OFF + 21888;       // 42912
constexpr int SMEM_FLOATS = WL3_OFF + 6912;    // 49824
constexpr int SMEM_BYTES  = SMEM_FLOATS * 4;   // 199296 B (< 227KB)

constexpr int H4OFF = 268;
}

// Weights, gate-interleaved: g_WT[(k*HH + j)*4 + g] per layer block; g in {i,f,g,o}
__device__ __align__(16) float g_WT[WT_TOTAL];
__device__ float g_Bias[B_TOTAL];

// ---------------------------------------------------------------------------
// Prep kernel: transpose to gate-interleaved [k][j][4] layout, fuse biases.
// ---------------------------------------------------------------------------
__global__ void prep_kernel(
    const float* __restrict__ Wih1, const float* __restrict__ Whh1,
    const float* __restrict__ bih1, const float* __restrict__ bhh1,
    const float* __restrict__ Wih2, const float* __restrict__ Whh2,
    const float* __restrict__ bih2, const float* __restrict__ bhh2,
    const float* __restrict__ Wih3, const float* __restrict__ Whh3,
    const float* __restrict__ bih3, const float* __restrict__ bhh3,
    const float* __restrict__ Wih4, const float* __restrict__ Whh4,
    const float* __restrict__ bih4, const float* __restrict__ bhh4)
{
    const float* Wih[4] = {Wih1, Wih2, Wih3, Wih4};
    const float* Whh[4] = {Whh1, Whh2, Whh3, Whh4};
    const float* bih[4] = {bih1, bih2, bih3, bih4};
    const float* bhh[4] = {bhh1, bhh2, bhh3, bhh4};

    const int lH[4]    = {90, 66, 48, 24};
    const int lDIN[4]  = {64, 90, 66, 48};
    const int lWOFF[4] = {0, 55440, 96624, 118512};
    const int lBOFF[4] = {0, 360, 624, 816};

    int idx = blockIdx.x * blockDim.x + threadIdx.x;
    if (idx < WT_TOTAL) {
        int l = (idx < lWOFF[1]) ? 0 : (idx < lWOFF[2]) ? 1 : (idx < lWOFF[3]) ? 2 : 3;
        int r  = idx - lWOFF[l];
        int f4 = r >> 2;
        int g  = r & 3;
        int k  = f4 / lH[l];
        int j  = f4 % lH[l];
        int n  = g * lH[l] + j;
        float v;
        if (k < lDIN[l]) v = Wih[l][n * lDIN[l] + k];
        else             v = Whh[l][n * lH[l] + (k - lDIN[l])];
        g_WT[idx] = v;
    } else if (idx < WT_TOTAL + B_TOTAL) {
        int bi = idx - WT_TOTAL;
        int l = (bi < lBOFF[1]) ? 0 : (bi < lBOFF[2]) ? 1 : (bi < lBOFF[3]) ? 2 : 3;
        int n = bi - lBOFF[l];
        g_Bias[bi] = bih[l][n] + bhh[l][n];
    }
}

// ---------------------------------------------------------------------------
// f32x2 helpers
// ---------------------------------------------------------------------------
DEVFN unsigned long long pk2(float lo, float hi) {
    unsigned long long u;
    asm("mov.b64 %0, {%1, %2};" : "=l"(u) : "f"(lo), "f"(hi));
    return u;
}
DEVFN float2 un2(unsigned long long u) {
    float2 v;
    asm("mov.b64 {%0, %1}, %2;" : "=f"(v.x), "=f"(v.y) : "l"(u));
    return v;
}
DEVFN void fma2(unsigned long long& d, unsigned long long a, unsigned long long b) {
    asm("fma.rn.f32x2 %0, %1, %2, %0;" : "+l"(d) : "l"(a), "l"(b));
}
DEVFN float sigf(float x)     { return __fdividef(1.0f, 1.0f + __expf(-x)); }
DEVFN float tanhfast(float x) { return __fdividef(2.0f, 1.0f + __expf(-2.0f * x)) - 1.0f; }

// ---------------------------------------------------------------------------
// One layer-stage for one thread: gates GEMM over KK inputs + cell update.
// Thread owns unit j, batch half [half*16, half*16+16) = 8 f32x2 pairs.
// Reads input window rows [SO, SO+KK) of pin; writes h row HO+j of pout.
// c lives in registers (c[8]).  GL: weights from global (L2$) vs smem.
// ---------------------------------------------------------------------------
template <int HH, int KK, int SO, int HO, bool GL>
DEVFN void do_layer(float4 bias, const float4* __restrict__ wj,
                    const float* pin, float* pout,
                    unsigned long long* c, int j, int half)
{
    unsigned long long acc[4][8];
#pragma unroll
    for (int p = 0; p < 8; ++p) {
        acc[0][p] = pk2(bias.x, bias.x);
        acc[1][p] = pk2(bias.y, bias.y);
        acc[2][p] = pk2(bias.z, bias.z);
        acc[3][p] = pk2(bias.w, bias.w);
    }

    const ulonglong2* pa =
        reinterpret_cast<const ulonglong2*>(pin) + SO * 9 + half * 4;

#pragma unroll 2
    for (int k = 0; k < KK; ++k) {
        float4 wv = GL ? __ldg(wj + k * HH) : wj[k * HH];
        ulonglong2 q0 = pa[k * 9 + 0];
        ulonglong2 q1 = pa[k * 9 + 1];
        ulonglong2 q2 = pa[k * 9 + 2];
        ulonglong2 q3 = pa[k * 9 + 3];
        unsigned long long p0 = pk2(wv.x, wv.x);
        unsigned long long p1 = pk2(wv.y, wv.y);
        unsigned long long p2 = pk2(wv.z, wv.z);
        unsigned long long p3 = pk2(wv.w, wv.w);
        fma2(acc[0][0], q0.x, p0); fma2(acc[0][1], q0.y, p0);
        fma2(acc[0][2], q1.x, p0); fma2(acc[0][3], q1.y, p0);
        fma2(acc[0][4], q2.x, p0); fma2(acc[0][5], q2.y, p0);
        fma2(acc[0][6], q3.x, p0); fma2(acc[0][7], q3.y, p0);
        fma2(acc[1][0], q0.x, p1); fma2(acc[1][1], q0.y, p1);
        fma2(acc[1][2], q1.x, p1); fma2(acc[1][3], q1.y, p1);
        fma2(acc[1][4], q2.x, p1); fma2(acc[1][5], q2.y, p1);
        fma2(acc[1][6], q3.x, p1); fma2(acc[1][7], q3.y, p1);
        fma2(acc[2][0], q0.x, p2); fma2(acc[2][1], q0.y, p2);
        fma2(acc[2][2], q1.x, p2); fma2(acc[2][3], q1.y, p2);
        fma2(acc[2][4], q2.x, p2); fma2(acc[2][5], q2.y, p2);
        fma2(acc[2][6], q3.x, p2); fma2(acc[2][7], q3.y, p2);
        fma2(acc[3][0], q0.x, p3); fma2(acc[3][1], q0.y, p3);
        fma2(acc[3][2], q1.x, p3); fma2(acc[3][3], q1.y, p3);
        fma2(acc[3][4], q2.x, p3); fma2(acc[3][5], q2.y, p3);
        fma2(acc[3][6], q3.x, p3); fma2(acc[3][7], q3.y, p3);
    }

    float hn[16];
#pragma unroll
    for (int p = 0; p < 8; ++p) {
        float2 iv = un2(acc[0][p]);
        float2 fv = un2(acc[1][p]);
        float2 gv = un2(acc[2][p]);
        float2 ov = un2(acc[3][p]);
        float2 cv = un2(c[p]);
        float c0 = sigf(fv.x) * cv.x + sigf(iv.x) * tanhfast(gv.x);
        float c1 = sigf(fv.y) * cv.y + sigf(iv.y) * tanhfast(gv.y);
        c[p] = pk2(c0, c1);
        hn[2 * p]     = sigf(ov.x) * tanhfast(c0);
        hn[2 * p + 1] = sigf(ov.y) * tanhfast(c1);
    }
    float* hp = pout + (HO + j) * SDIM + half * 16;
    *reinterpret_cast<float4*>(hp)      = *reinterpret_cast<const float4*>(hn);
    *reinterpret_cast<float4*>(hp + 4)  = *reinterpret_cast<const float4*>(hn + 4);
    *reinterpret_cast<float4*>(hp + 8)  = *reinterpret_cast<const float4*>(hn + 8);
    *reinterpret_cast<float4*>(hp + 12) = *reinterpret_cast<const float4*>(hn + 12);
}

// ---------------------------------------------------------------------------
// Persistent main kernel: one CTA = 32 batch rows; layers software-pipelined
// over stages (L_l at stage s handles timestep s-l).  One barrier per stage.
// ---------------------------------------------------------------------------
__global__ void __launch_bounds__(NTHREADS, 1)
lstm_main(const float* __restrict__ x,
          const float* __restrict__ fcw,
          const float* __restrict__ fcb,
          float* __restrict__ out)
{
    extern __shared__ float sm[];

    const int tid  = threadIdx.x;
    const int w    = tid >> 5;
    const int lane = tid & 31;
    const int b0   = blockIdx.x * MTILE;

    // warp -> (layer, local index): balances FFMA2 load across SMSPs
    const int wlayerA[16] = {1,0,0,0, 1,0,0,0, 2,1,1,1, 3,2,3,2};
    const int wlocA[16]   = {0,0,1,2, 1,3,4,5, 0,2,3,4, 0,1,1,2};
    const int lyr = wlayerA[w];
    const int loc = wlocA[w];
    const int j    = loc * 16 + (lane >> 1);
    const int half = lane & 1;

    const int HHt[4] = {90, 66, 48, 24};
    const int BOt[4] = {0, 360, 624, 816};
    const int HH = HHt[lyr];
    const bool on = (j < HH);

    float4 bias = make_float4(0.f, 0.f, 0.f, 0.f);
    if (on) {
        const int BO = BOt[lyr];
        bias = make_float4(g_Bias[BO + j], g_Bias[BO + HH + j],
                           g_Bias[BO + 2 * HH + j], g_Bias[BO + 3 * HH + j]);
    }

    // stage L2/L3 weights into smem
    {
        const float4* gw4 = reinterpret_cast<const float4*>(g_WT);
        float4* w2 = reinterpret_cast<float4*>(sm + WL2_OFF);
        float4* w3 = reinterpret_cast<float4*>(sm + WL3_OFF);
        for (int i = tid; i < 5472; i += NTHREADS) w2[i] = gw4[24156 + i];
        for (int i = tid; i < 1728; i += NTHREADS) w3[i] = gw4[29628 + i];
    }
    // zero both state parities
    for (int i = tid; i < 2 * PSTRIDE; i += NTHREADS) sm[i] = 0.0f;

    // weight pointer for this thread's layer (float4 units, element k at wj[k*HH])
    const float4* gw = reinterpret_cast<const float4*>(g_WT);
    const float4* wj;
    if      (lyr == 0) wj = gw + j;
    else if (lyr == 1) wj = gw + 13860 + j;
    else if (lyr == 2) wj = reinterpret_cast<const float4*>(sm + WL2_OFF) + j;
    else               wj = reinterpret_cast<const float4*>(sm + WL3_OFF) + j;

    // stage x[0] into parity 1 (read by L0 at stage 0)
    const float* xrow = x + (size_t)(b0 + lane) * Tlen * IND + 4 * w;
    {
        float4 xv = *reinterpret_cast<const float4*>(xrow);
        float* p1 = sm + PSTRIDE;
        p1[(4 * w + 0) * SDIM + lane] = xv.x;
        p1[(4 * w + 1) * SDIM + lane] = xv.y;
        p1[(4 * w + 2) * SDIM + lane] = xv.z;
        p1[(4 * w + 3) * SDIM + lane] = xv.w;
    }
    __syncthreads();

    unsigned long long c[8];
#pragma unroll
    for (int p = 0; p < 8; ++p) c[p] = 0ull;

    for (int s = 0; s < NSTAGES; ++s) {
        const float* pin  = sm + ((s + 1) & 1) * PSTRIDE;  // == (s-1)&1
        float*       pout = sm + (s & 1) * PSTRIDE;

        // prefetch next x tile (goes to pout's x rows: parity s&1 read at s+1)
        float4 xv;
        const bool stx = (s < Tlen - 1);
        if (stx) xv = *reinterpret_cast<const float4*>(xrow + (size_t)(s + 1) * IND);

        const bool act = on && (s >= lyr) && (s - lyr < Tlen);
        if (act) {
            if      (lyr == 0) do_layer<90, 154,   0,  64, true >(bias, wj, pin, pout, c, j, half);
            else if (lyr == 1) do_layer<66, 156,  64, 154, true >(bias, wj, pin, pout, c, j, half);
            else if (lyr == 2) do_layer<48, 114, 154, 220, false>(bias, wj, pin, pout, c, j, half);
            else               do_layer<24,  72, 220, 268, false>(bias, wj, pin, pout, c, j, half);
        }

        if (stx) {
            pout[(4 * w + 0) * SDIM + lane] = xv.x;
            pout[(4 * w + 1) * SDIM + lane] = xv.y;
            pout[(4 * w + 2) * SDIM + lane] = xv.z;
            pout[(4 * w + 3) * SDIM + lane] = xv.w;
        }
        __syncthreads();
    }

    // h4[T-1] written at stage 514 -> parity 0
    if (tid < 32) {
        float acc = fcb[0];
#pragma unroll
        for (int jj = 0; jj < 24; ++jj)
            acc += sm[(H4OFF + jj) * SDIM + tid] * fcw[jj];
        out[b0 + tid] = acc;
    }
}

// ---------------------------------------------------------------------------
extern "C" void kernel_launch(void* const* d_in, const int* in_sizes, int n_in,
                              void* d_out, int out_size)
{
    (void)in_sizes; (void)n_in; (void)out_size;
    const float* x    = (const float*)d_in[0];
    const float* Wih1 = (const float*)d_in[1];
    const float* Whh1 = (const float*)d_in[2];
    const float* bih1 = (const float*)d_in[3];
    const float* bhh1 = (const float*)d_in[4];
    const float* Wih2 = (const float*)d_in[5];
    const float* Whh2 = (const float*)d_in[6];
    const float* bih2 = (const float*)d_in[7];
    const float* bhh2 = (const float*)d_in[8];
    const float* Wih3 = (const float*)d_in[9];
    const float* Whh3 = (const float*)d_in[10];
    const float* bih3 = (const float*)d_in[11];
    const float* bhh3 = (const float*)d_in[12];
    const float* Wih4 = (const float*)d_in[13];
    const float* Whh4 = (const float*)d_in[14];
    const float* bih4 = (const float*)d_in[15];
    const float* bhh4 = (const float*)d_in[16];
    const float* fcw  = (const float*)d_in[17];
    const float* fcb  = (const float*)d_in[18];

    static bool attr_done = false;
    if (!attr_done) {
        cudaFuncSetAttribute(lstm_main,
                             cudaFuncAttributeMaxDynamicSharedMemorySize,
                             SMEM_BYTES);
        attr_done = true;
    }

    const int prep_total = WT_TOTAL + B_TOTAL;
    prep_kernel<<<(prep_total + 255) / 256, 256>>>(
        Wih1, Whh1, bih1, bhh1, Wih2, Whh2, bih2, bhh2,
        Wih3, Whh3, bih3, bhh3, Wih4, Whh4, bih4, bhh4);

    lstm_main<<<NBLOCKS, NTHREADS, SMEM_BYTES>>>(x, fcw, fcb, (float*)d_out);
}

// round 11
// speedup vs baseline: 2.5650x; 1.2437x over previous
#include <cuda_runtime.h>
#include <cstddef>

#define DEVFN __device__ __forceinline__

namespace {
constexpr int Bsz  = 4096;
constexpr int Tlen = 512;
constexpr int IND  = 64;

constexpr int WT_TOTAL = 125424;
constexpr int B_TOTAL  = 912;

// state row layout (per parity): x[0,64) h1[64,154) h2[154,220) h3[220,268) h4[268,292)
constexpr int SROWS = 292;
constexpr int SDIM  = 36;                      // 144B rows, 16B aligned
constexpr int PSTRIDE = SROWS * SDIM;          // 10512 floats per parity
constexpr int MTILE = 32;
constexpr int NTHREADS = 512;
constexpr int NBLOCKS  = Bsz / MTILE;          // 128
constexpr int NSTAGES  = Tlen + 3;             // 515

// smem layout (float offsets): parity0 | parity1 | WL2 | WL3
constexpr int WL2_OFF = 2 * PSTRIDE;           // 21024
constexpr int WL3_OFF = WL2_OFF + 21888;       // 42912
constexpr int SMEM_FLOATS = WL3_OFF + 6912;    // 49824
constexpr int SMEM_BYTES  = SMEM_FLOATS * 4;   // 199296 B (< 227KB)

constexpr int H4OFF = 268;
}

// Weights, gate-interleaved: g_WT[(k*HH + j)*4 + g] per layer block; g in {i,f,g,o}
__device__ __align__(16) float g_WT[WT_TOTAL];
__device__ float g_Bias[B_TOTAL];

// ---------------------------------------------------------------------------
// Prep kernel: transpose to gate-interleaved [k][j][4] layout, fuse biases.
// ---------------------------------------------------------------------------
__global__ void prep_kernel(
    const float* __restrict__ Wih1, const float* __restrict__ Whh1,
    const float* __restrict__ bih1, const float* __restrict__ bhh1,
    const float* __restrict__ Wih2, const float* __restrict__ Whh2,
    const float* __restrict__ bih2, const float* __restrict__ bhh2,
    const float* __restrict__ Wih3, const float* __restrict__ Whh3,
    const float* __restrict__ bih3, const float* __restrict__ bhh3,
    const float* __restrict__ Wih4, const float* __restrict__ Whh4,
    const float* __restrict__ bih4, const float* __restrict__ bhh4)
{
    const float* Wih[4] = {Wih1, Wih2, Wih3, Wih4};
    const float* Whh[4] = {Whh1, Whh2, Whh3, Whh4};
    const float* bih[4] = {bih1, bih2, bih3, bih4};
    const float* bhh[4] = {bhh1, bhh2, bhh3, bhh4};

    const int lH[4]    = {90, 66, 48, 24};
    const int lDIN[4]  = {64, 90, 66, 48};
    const int lWOFF[4] = {0, 55440, 96624, 118512};
    const int lBOFF[4] = {0, 360, 624, 816};

    int idx = blockIdx.x * blockDim.x + threadIdx.x;
    if (idx < WT_TOTAL) {
        int l = (idx < lWOFF[1]) ? 0 : (idx < lWOFF[2]) ? 1 : (idx < lWOFF[3]) ? 2 : 3;
        int r  = idx - lWOFF[l];
        int f4 = r >> 2;
        int g  = r & 3;
        int k  = f4 / lH[l];
        int j  = f4 % lH[l];
        int n  = g * lH[l] + j;
        float v;
        if (k < lDIN[l]) v = Wih[l][n * lDIN[l] + k];
        else             v = Whh[l][n * lH[l] + (k - lDIN[l])];
        g_WT[idx] = v;
    } else if (idx < WT_TOTAL + B_TOTAL) {
        int bi = idx - WT_TOTAL;
        int l = (bi < lBOFF[1]) ? 0 : (bi < lBOFF[2]) ? 1 : (bi < lBOFF[3]) ? 2 : 3;
        int n = bi - lBOFF[l];
        g_Bias[bi] = bih[l][n] + bhh[l][n];
    }
}

// ---------------------------------------------------------------------------
// f32x2 helpers
// ---------------------------------------------------------------------------
DEVFN unsigned long long pk2(float lo, float hi) {
    unsigned long long u;
    asm("mov.b64 %0, {%1, %2};" : "=l"(u) : "f"(lo), "f"(hi));
    return u;
}
DEVFN float2 un2(unsigned long long u) {
    float2 v;
    asm("mov.b64 {%0, %1}, %2;" : "=f"(v.x), "=f"(v.y) : "l"(u));
    return v;
}
DEVFN void fma2(unsigned long long& d, unsigned long long a, unsigned long long b) {
    asm("fma.rn.f32x2 %0, %1, %2, %0;" : "+l"(d) : "l"(a), "l"(b));
}
DEVFN float sigf(float x)     { return __fdividef(1.0f, 1.0f + __expf(-x)); }
DEVFN float tanhfast(float x) { return __fdividef(2.0f, 1.0f + __expf(-2.0f * x)) - 1.0f; }

// one k-step of the gates GEMM (32 FFMA2)
DEVFN void kstep(unsigned long long acc[4][8], const ulonglong2* pa,
                 int k, float4 wv)
{
    ulonglong2 q0 = pa[k * 9 + 0];
    ulonglong2 q1 = pa[k * 9 + 1];
    ulonglong2 q2 = pa[k * 9 + 2];
    ulonglong2 q3 = pa[k * 9 + 3];
    unsigned long long p0 = pk2(wv.x, wv.x);
    unsigned long long p1 = pk2(wv.y, wv.y);
    unsigned long long p2 = pk2(wv.z, wv.z);
    unsigned long long p3 = pk2(wv.w, wv.w);
    fma2(acc[0][0], q0.x, p0); fma2(acc[0][1], q0.y, p0);
    fma2(acc[0][2], q1.x, p0); fma2(acc[0][3], q1.y, p0);
    fma2(acc[0][4], q2.x, p0); fma2(acc[0][5], q2.y, p0);
    fma2(acc[0][6], q3.x, p0); fma2(acc[0][7], q3.y, p0);
    fma2(acc[1][0], q0.x, p1); fma2(acc[1][1], q0.y, p1);
    fma2(acc[1][2], q1.x, p1); fma2(acc[1][3], q1.y, p1);
    fma2(acc[1][4], q2.x, p1); fma2(acc[1][5], q2.y, p1);
    fma2(acc[1][6], q3.x, p1); fma2(acc[1][7], q3.y, p1);
    fma2(acc[2][0], q0.x, p2); fma2(acc[2][1], q0.y, p2);
    fma2(acc[2][2], q1.x, p2); fma2(acc[2][3], q1.y, p2);
    fma2(acc[2][4], q2.x, p2); fma2(acc[2][5], q2.y, p2);
    fma2(acc[2][6], q3.x, p2); fma2(acc[2][7], q3.y, p2);
    fma2(acc[3][0], q0.x, p3); fma2(acc[3][1], q0.y, p3);
    fma2(acc[3][2], q1.x, p3); fma2(acc[3][3], q1.y, p3);
    fma2(acc[3][4], q2.x, p3); fma2(acc[3][5], q2.y, p3);
    fma2(acc[3][6], q3.x, p3); fma2(acc[3][7], q3.y, p3);
}

// ---------------------------------------------------------------------------
// One layer-stage for one thread: gates GEMM over KK inputs + cell update.
// Thread owns unit j, batch half [half*16, half*16+16) = 8 f32x2 pairs.
// GL path: 2-deep register prefetch pipeline on the weight LDG stream so the
// ~234-cycle L2 latency is covered by ~2 k-iters of FMA work.  KK is even for
// all layers, so the k-loop steps by 2 with static buffer indices (no tail).
// Overreads at k = KK..KK+1 stay inside g_WT (values never used).
// ---------------------------------------------------------------------------
template <int HH, int KK, int SO, int HO, bool GL>
DEVFN void do_layer(float4 bias, const float4* __restrict__ wj,
                    const float* pin, float* pout,
                    unsigned long long* c, int j, int half)
{
    unsigned long long acc[4][8];
#pragma unroll
    for (int p = 0; p < 8; ++p) {
        acc[0][p] = pk2(bias.x, bias.x);
        acc[1][p] = pk2(bias.y, bias.y);
        acc[2][p] = pk2(bias.z, bias.z);
        acc[3][p] = pk2(bias.w, bias.w);
    }

    const ulonglong2* pa =
        reinterpret_cast<const ulonglong2*>(pin) + SO * 9 + half * 4;

    static_assert((KK & 1) == 0, "KK must be even");

    if (GL) {
        float4 wb0 = __ldg(wj);
        float4 wb1 = __ldg(wj + HH);
#pragma unroll 2
        for (int kb = 0; kb < KK / 2; ++kb) {
            const int k0 = 2 * kb;
            float4 wv0 = wb0;
            float4 wv1 = wb1;
            wb0 = __ldg(wj + (k0 + 2) * HH);
            wb1 = __ldg(wj + (k0 + 3) * HH);
            kstep(acc, pa, k0, wv0);
            kstep(acc, pa, k0 + 1, wv1);
        }
    } else {
#pragma unroll 4
        for (int k = 0; k < KK; ++k)
            kstep(acc, pa, k, wj[k * HH]);
    }

    float hn[16];
#pragma unroll
    for (int p = 0; p < 8; ++p) {
        float2 iv = un2(acc[0][p]);
        float2 fv = un2(acc[1][p]);
        float2 gv = un2(acc[2][p]);
        float2 ov = un2(acc[3][p]);
        float2 cv = un2(c[p]);
        float c0 = sigf(fv.x) * cv.x + sigf(iv.x) * tanhfast(gv.x);
        float c1 = sigf(fv.y) * cv.y + sigf(iv.y) * tanhfast(gv.y);
        c[p] = pk2(c0, c1);
        hn[2 * p]     = sigf(ov.x) * tanhfast(c0);
        hn[2 * p + 1] = sigf(ov.y) * tanhfast(c1);
    }
    float* hp = pout + (HO + j) * SDIM + half * 16;
    *reinterpret_cast<float4*>(hp)      = *reinterpret_cast<const float4*>(hn);
    *reinterpret_cast<float4*>(hp + 4)  = *reinterpret_cast<const float4*>(hn + 4);
    *reinterpret_cast<float4*>(hp + 8)  = *reinterpret_cast<const float4*>(hn + 8);
    *reinterpret_cast<float4*>(hp + 12) = *reinterpret_cast<const float4*>(hn + 12);
}

// ---------------------------------------------------------------------------
// Persistent main kernel: one CTA = 32 batch rows; layers software-pipelined
// over stages (L_l at stage s handles timestep s-l).  One barrier per stage.
// ---------------------------------------------------------------------------
__global__ void __launch_bounds__(NTHREADS, 1)
lstm_main(const float* __restrict__ x,
          const float* __restrict__ fcw,
          const float* __restrict__ fcb,
          float* __restrict__ out)
{
    extern __shared__ float sm[];

    const int tid  = threadIdx.x;
    const int w    = tid >> 5;
    const int lane = tid & 31;
    const int b0   = blockIdx.x * MTILE;

    // warp -> (layer, local index): balances FFMA2 load across SMSPs
    const int wlayerA[16] = {1,0,0,0, 1,0,0,0, 2,1,1,1, 3,2,3,2};
    const int wlocA[16]   = {0,0,1,2, 1,3,4,5, 0,2,3,4, 0,1,1,2};
    const int lyr = wlayerA[w];
    const int loc = wlocA[w];
    const int j    = loc * 16 + (lane >> 1);
    const int half = lane & 1;

    const int HHt[4] = {90, 66, 48, 24};
    const int BOt[4] = {0, 360, 624, 816};
    const int HH = HHt[lyr];
    const bool on = (j < HH);

    float4 bias = make_float4(0.f, 0.f, 0.f, 0.f);
    if (on) {
        const int BO = BOt[lyr];
        bias = make_float4(g_Bias[BO + j], g_Bias[BO + HH + j],
                           g_Bias[BO + 2 * HH + j], g_Bias[BO + 3 * HH + j]);
    }

    // stage L2/L3 weights into smem
    {
        const float4* gw4 = reinterpret_cast<const float4*>(g_WT);
        float4* w2 = reinterpret_cast<float4*>(sm + WL2_OFF);
        float4* w3 = reinterpret_cast<float4*>(sm + WL3_OFF);
        for (int i = tid; i < 5472; i += NTHREADS) w2[i] = gw4[24156 + i];
        for (int i = tid; i < 1728; i += NTHREADS) w3[i] = gw4[29628 + i];
    }
    // zero both state parities
    for (int i = tid; i < 2 * PSTRIDE; i += NTHREADS) sm[i] = 0.0f;

    // weight pointer for this thread's layer (float4 units, element k at wj[k*HH])
    const float4* gw = reinterpret_cast<const float4*>(g_WT);
    const float4* wj;
    if      (lyr == 0) wj = gw + j;
    else if (lyr == 1) wj = gw + 13860 + j;
    else if (lyr == 2) wj = reinterpret_cast<const float4*>(sm + WL2_OFF) + j;
    else               wj = reinterpret_cast<const float4*>(sm + WL3_OFF) + j;

    // stage x[0] into parity 1 (read by L0 at stage 0)
    const float* xrow = x + (size_t)(b0 + lane) * Tlen * IND + 4 * w;
    {
        float4 xv = *reinterpret_cast<const float4*>(xrow);
        float* p1 = sm + PSTRIDE;
        p1[(4 * w + 0) * SDIM + lane] = xv.x;
        p1[(4 * w + 1) * SDIM + lane] = xv.y;
        p1[(4 * w + 2) * SDIM + lane] = xv.z;
        p1[(4 * w + 3) * SDIM + lane] = xv.w;
    }
    __syncthreads();

    unsigned long long c[8];
#pragma unroll
    for (int p = 0; p < 8; ++p) c[p] = 0ull;

    for (int s = 0; s < NSTAGES; ++s) {
        const float* pin  = sm + ((s + 1) & 1) * PSTRIDE;  // == (s-1)&1
        float*       pout = sm + (s & 1) * PSTRIDE;

        // prefetch next x tile (goes to pout's x rows: parity s&1 read at s+1)
        float4 xv;
        const bool stx = (s < Tlen - 1);
        if (stx) xv = *reinterpret_cast<const float4*>(xrow + (size_t)(s + 1) * IND);

        const bool act = on && (s >= lyr) && (s - lyr < Tlen);
        if (act) {
            if      (lyr == 0) do_layer<90, 154,   0,  64, true >(bias, wj, pin, pout, c, j, half);
            else if (lyr == 1) do_layer<66, 156,  64, 154, true >(bias, wj, pin, pout, c, j, half);
            else if (lyr == 2) do_layer<48, 114, 154, 220, false>(bias, wj, pin, pout, c, j, half);
            else               do_layer<24,  72, 220, 268, false>(bias, wj, pin, pout, c, j, half);
        }

        if (stx) {
            pout[(4 * w + 0) * SDIM + lane] = xv.x;
            pout[(4 * w + 1) * SDIM + lane] = xv.y;
            pout[(4 * w + 2) * SDIM + lane] = xv.z;
            pout[(4 * w + 3) * SDIM + lane] = xv.w;
        }
        __syncthreads();
    }

    // h4[T-1] written at stage 514 -> parity 0
    if (tid < 32) {
        float acc = fcb[0];
#pragma unroll
        for (int jj = 0; jj < 24; ++jj)
            acc += sm[(H4OFF + jj) * SDIM + tid] * fcw[jj];
        out[b0 + tid] = acc;
    }
}

// ---------------------------------------------------------------------------
extern "C" void kernel_launch(void* const* d_in, const int* in_sizes, int n_in,
                              void* d_out, int out_size)
{
    (void)in_sizes; (void)n_in; (void)out_size;
    const float* x    = (const float*)d_in[0];
    const float* Wih1 = (const float*)d_in[1];
    const float* Whh1 = (const float*)d_in[2];
    const float* bih1 = (const float*)d_in[3];
    const float* bhh1 = (const float*)d_in[4];
    const float* Wih2 = (const float*)d_in[5];
    const float* Whh2 = (const float*)d_in[6];
    const float* bih2 = (const float*)d_in[7];
    const float* bhh2 = (const float*)d_in[8];
    const float* Wih3 = (const float*)d_in[9];
    const float* Whh3 = (const float*)d_in[10];
    const float* bih3 = (const float*)d_in[11];
    const float* bhh3 = (const float*)d_in[12];
    const float* Wih4 = (const float*)d_in[13];
    const float* Whh4 = (const float*)d_in[14];
    const float* bih4 = (const float*)d_in[15];
    const float* bhh4 = (const float*)d_in[16];
    const float* fcw  = (const float*)d_in[17];
    const float* fcb  = (const float*)d_in[18];

    static bool attr_done = false;
    if (!attr_done) {
        cudaFuncSetAttribute(lstm_main,
                             cudaFuncAttributeMaxDynamicSharedMemorySize,
                             SMEM_BYTES);
        attr_done = true;
    }

    const int prep_total = WT_TOTAL + B_TOTAL;
    prep_kernel<<<(prep_total + 255) / 256, 256>>>(
        Wih1, Whh1, bih1, bhh1, Wih2, Whh2, bih2, bhh2,
        Wih3, Whh3, bih3, bhh3, Wih4, Whh4, bih4, bhh4);

    lstm_main<<<NBLOCKS, NTHREADS, SMEM_BYTES>>>(x, fcw, fcb, (float*)d_out);
}